// round 15
// baseline (speedup 1.0000x reference)
#include <cuda_runtime.h>
#include <cuda_bf16.h>
#include <cstdint>
#include <math.h>

#define NN 32
#define TT 243
#define VV 17
#define DD 512
#define DM 384
#define DA 128
#define NH 4
#define HD 32
#define BT (NN*TT)               // 7776 slices
#define ROW_ELEMS (VV*DD)
#define MROWS (BT*VV)            // 132192
#define MPADT 1033
#define MPAD  (MPADT*128)

typedef unsigned long long ull;

// ---- global scratch (static device arrays; zero-initialized) ----
__device__ __nv_bfloat16 g_xn [(size_t)MPAD * 512];
__device__ __nv_bfloat16 g_h  [(size_t)MPAD * 1024];
__device__ __nv_bfloat16 g_w1 [1024 * 512];
__device__ __nv_bfloat16 g_w2 [512 * 1024];
__device__ float         g_xc [(size_t)MROWS * 512];
__device__ __nv_bfloat16 g_xa [(size_t)MPAD * 128];
__device__ __nv_bfloat16 g_qkv[(size_t)MPAD * 384];
__device__ __nv_bfloat16 g_o  [(size_t)MPAD * 128];
__device__ __nv_bfloat16 g_wqb[384 * 128];
__device__ __nv_bfloat16 g_wob[128 * 128];

__device__ __forceinline__ ull pack2(float lo, float hi) {
    ull r; asm("mov.b64 %0, {%1, %2};" : "=l"(r) : "f"(lo), "f"(hi)); return r;
}
__device__ __forceinline__ float2 unpack2(ull v) {
    float2 r; asm("mov.b64 {%0, %1}, %2;" : "=f"(r.x), "=f"(r.y) : "l"(v)); return r;
}
__device__ __forceinline__ void ffma2(ull& acc, ull a, ull b) {
    asm("fma.rn.f32x2 %0, %1, %2, %0;" : "+l"(acc) : "l"(a), "l"(b));
}
__device__ __forceinline__ float gelu_exact(float v) {
    return 0.5f * v * (1.0f + erff(v * 0.7071067811865475f));
}
__device__ __forceinline__ void cp_commit() {
    asm volatile("cp.async.commit_group;" ::: "memory");
}
__device__ __forceinline__ void cp_wait0() { asm volatile("cp.async.wait_group 0;" ::: "memory"); }
__device__ __forceinline__ void cp_wait1() { asm volatile("cp.async.wait_group 1;" ::: "memory"); }
__device__ __forceinline__ void cp_async16(unsigned dst, const void* src) {
    asm volatile("cp.async.cg.shared.global [%0], [%1], 16;" :: "r"(dst), "l"(src));
}
#define SWZ128(off) ((off) ^ (((off) >> 3) & 0x70))

// ==================== weight convert ====================
extern "C" __global__ void convert_weights(const float* __restrict__ w1,
                                           const float* __restrict__ w2,
                                           const float* __restrict__ in_w,
                                           const float* __restrict__ out_w)
{
    int i = blockIdx.x * 256 + threadIdx.x;
    if (i < 1024 * 512) g_w1[i] = __float2bfloat16(w1[i]);
    if (i < 512 * 1024) g_w2[i] = __float2bfloat16(w2[i]);
    if (i < 384 * 128)  g_wqb[i] = __float2bfloat16(in_w[i]);
    if (i < 128 * 128)  g_wob[i] = __float2bfloat16(out_w[i]);
}

// ==================== K1a: token mixer (registers), 384 threads ====================
extern "C" __global__ void __launch_bounds__(384, 2)
k1_mix(const float* __restrict__ x,
       const float* __restrict__ tm_w1, const float* __restrict__ tm_b1,
       const float* __restrict__ tm_w2, const float* __restrict__ tm_b2)
{
    __shared__ float w1s[17 * 18], w2s[17 * 18], b1s[17], b2s[17];
    const int tid = threadIdx.x;
    const size_t base = (size_t)blockIdx.x * ROW_ELEMS;
    const float* xg = x + base;

    for (int i = tid; i < 289; i += 384) {
        int u = i / 17, v = i - u * 17;
        w1s[u * 18 + v] = tm_w1[i];
        w2s[u * 18 + v] = tm_w2[i];
    }
    if (tid < 17) { b1s[tid] = tm_b1[tid]; b2s[tid] = tm_b2[tid]; }
    __syncthreads();

    const int d = tid;
    float xr[17];
    #pragma unroll
    for (int v = 0; v < VV; v++) xr[v] = xg[v * DD + d];
    ull xp[8];
    #pragma unroll
    for (int p = 0; p < 8; p++) xp[p] = pack2(xr[2 * p], xr[2 * p + 1]);

    float h[17];
    #pragma unroll
    for (int u = 0; u < VV; u++) {
        ull a2 = 0ull;
        const float* wr = w1s + u * 18;
        #pragma unroll
        for (int p = 0; p < 8; p++) ffma2(a2, xp[p], *(const ull*)(wr + 2 * p));
        float2 s = unpack2(a2);
        h[u] = gelu_exact(s.x + s.y + xr[16] * wr[16] + b1s[u]);
    }
    ull hp[8];
    #pragma unroll
    for (int p = 0; p < 8; p++) hp[p] = pack2(h[2 * p], h[2 * p + 1]);

    float* oc = g_xc + (size_t)blockIdx.x * VV * DD + d;
    #pragma unroll
    for (int u = 0; u < VV; u++) {
        ull a2 = 0ull;
        const float* wr = w2s + u * 18;
        #pragma unroll
        for (int p = 0; p < 8; p++) ffma2(a2, hp[p], *(const ull*)(wr + 2 * p));
        float2 s = unpack2(a2);
        oc[(size_t)u * DD] = s.x + s.y + h[16] * wr[16] + b2s[u];
    }
}

// ==================== K1b: rmsnorm(xa) -> bf16, 128 threads ====================
extern "C" __global__ void __launch_bounds__(128, 8)
k1_xa(const float* __restrict__ x, const float* __restrict__ na_w)
{
    const int warp = threadIdx.x >> 5, lane = threadIdx.x & 31;
    const float* xg = x + (size_t)blockIdx.x * ROW_ELEMS + DM;
    for (int r = warp; r < VV; r += 4) {
        float vals[4]; float s = 0.f;
        #pragma unroll
        for (int q = 0; q < 4; q++) {
            float t = xg[r * DD + lane + 32 * q];
            vals[q] = t; s += t * t;
        }
        #pragma unroll
        for (int o = 16; o; o >>= 1) s += __shfl_xor_sync(0xffffffffu, s, o);
        float rms = rsqrtf(s * (1.0f / DA) + 1e-6f);
        __nv_bfloat16* oa = g_xa + ((size_t)blockIdx.x * VV + r) * DA;
        #pragma unroll
        for (int q = 0; q < 4; q++) {
            int c = lane + 32 * q;
            oa[c] = __float2bfloat16(vals[q] * rms * na_w[c]);
        }
    }
}

// ==================== K_att2: scores + softmax + o ====================
#define QLD 388
extern "C" __global__ void __launch_bounds__(128)
k_att2()
{
    __shared__ float qkv_s[VV * QLD];
    __shared__ float sc[NH * VV * VV];

    const int tid = threadIdx.x;
    const size_t bid = blockIdx.x;

    // load qkv rows (17 x 384 bf16) -> fp32 smem
    {
        const __nv_bfloat16* src = g_qkv + bid * (VV * 384);
        #pragma unroll 4
        for (int i = tid; i < VV * 48; i += 128) {
            int v = i / 48, c = i - v * 48;
            uint4 raw = *(const uint4*)(src + v * 384 + c * 8);
            const __nv_bfloat162* b2 = (const __nv_bfloat162*)&raw;
            float* dst = qkv_s + v * QLD + c * 8;
            #pragma unroll
            for (int q = 0; q < 4; q++) {
                float2 f = __bfloat1622float2(b2[q]);
                dst[2 * q] = f.x; dst[2 * q + 1] = f.y;
            }
        }
    }
    __syncthreads();

    for (int k = tid; k < NH * VV * VV; k += 128) {
        int h = k / (VV * VV), r = k - h * VV * VV, qv = r / VV, kv = r - qv * VV;
        const float4* qp = (const float4*)(qkv_s + qv * QLD + h * HD);
        const float4* kp = (const float4*)(qkv_s + kv * QLD + DA + h * HD);
        float s = 0.f;
        #pragma unroll
        for (int d = 0; d < 8; d++) {
            float4 a = qp[d], b = kp[d];
            s += a.x * b.x + a.y * b.y + a.z * b.z + a.w * b.w;
        }
        sc[k] = s * 0.17677669529663687f;
    }
    __syncthreads();

    for (int r = tid; r < NH * VV; r += 128) {
        float* row = sc + r * VV;
        float m = row[0];
        #pragma unroll
        for (int i = 1; i < VV; i++) m = fmaxf(m, row[i]);
        float s = 0.f;
        #pragma unroll
        for (int i = 0; i < VV; i++) { float e = __expf(row[i] - m); row[i] = e; s += e; }
        float inv = 1.f / s;
        #pragma unroll
        for (int i = 0; i < VV; i++) row[i] *= inv;
    }
    __syncthreads();

    // o = attn @ v, kv-outer loop: 306 LDS/thread instead of 578
    {
        const int dd = tid, h = dd >> 5;
        float acc[VV];
        #pragma unroll
        for (int vq = 0; vq < VV; vq++) acc[vq] = 0.f;
        #pragma unroll 1
        for (int kv = 0; kv < VV; kv++) {
            float v = qkv_s[kv * QLD + 2 * DA + dd];
            const float* sch = sc + h * VV * VV + kv;
            #pragma unroll
            for (int vq = 0; vq < VV; vq++)
                acc[vq] += sch[vq * VV] * v;   // warp-broadcast
        }
        __nv_bfloat16* og = g_o + bid * (VV * DA) + dd;
        #pragma unroll
        for (int vq = 0; vq < VV; vq++)
            og[(size_t)vq * DA] = __float2bfloat16(acc[vq]);
    }
}

// ==================== K_norm ====================
extern "C" __global__ void __launch_bounds__(256)
k_norm(const float* __restrict__ nf_w)
{
    const int warp = threadIdx.x >> 5, lane = threadIdx.x & 31;
    const size_t row = (size_t)blockIdx.x * 8 + warp;
    const float* src = g_xc + row * DD;
    float4 v[4]; float s = 0.f;
    #pragma unroll
    for (int q = 0; q < 4; q++) {
        v[q] = *(const float4*)(src + (lane + 32 * q) * 4);
        s += v[q].x * v[q].x + v[q].y * v[q].y + v[q].z * v[q].z + v[q].w * v[q].w;
    }
    #pragma unroll
    for (int o = 16; o; o >>= 1) s += __shfl_xor_sync(0xffffffffu, s, o);
    float r = rsqrtf(s * (1.0f / DD) + 1e-6f);
    __nv_bfloat16* dst = g_xn + row * DD;
    #pragma unroll
    for (int q = 0; q < 4; q++) {
        int c = (lane + 32 * q) * 4;
        const float4 wv = *(const float4*)(nf_w + c);
        __nv_bfloat162 p0 = __floats2bfloat162_rn(v[q].x * r * wv.x, v[q].y * r * wv.y);
        __nv_bfloat162 p1 = __floats2bfloat162_rn(v[q].z * r * wv.z, v[q].w * r * wv.w);
        *reinterpret_cast<__nv_bfloat162*>(dst + c)     = p0;
        *reinterpret_cast<__nv_bfloat162*>(dst + c + 2) = p1;
    }
}

// ============================ common MMA helpers ============================
__device__ __forceinline__ void ldsm4(unsigned* r, unsigned addr) {
    asm volatile("ldmatrix.sync.aligned.m8n8.x4.shared.b16 {%0,%1,%2,%3}, [%4];"
        : "=r"(r[0]), "=r"(r[1]), "=r"(r[2]), "=r"(r[3]) : "r"(addr));
}
__device__ __forceinline__ void mma16816(float* c, const unsigned* a, const unsigned* b) {
    asm volatile("mma.sync.aligned.m16n8k16.row.col.f32.bf16.bf16.f32 "
        "{%0,%1,%2,%3}, {%4,%5,%6,%7}, {%8,%9}, {%0,%1,%2,%3};"
        : "+f"(c[0]), "+f"(c[1]), "+f"(c[2]), "+f"(c[3])
        : "r"(a[0]), "r"(a[1]), "r"(a[2]), "r"(a[3]), "r"(b[0]), "r"(b[1]));
}

// ============================ v3 GEMM: 256 thr, 128x128 (measured 42.4%) ============================
#define V3KC 64
#define V3SRG 72
#define V3TILE_B ((unsigned)(128 * V3SRG * 2))
#define V3STAGE_B (2u * V3TILE_B)
#define V3SMEM (3 * 2 * 128 * V3SRG * 2)

// EPI 1: gelu(+bias) -> bf16 ldc 1024;  EPI 2: +bias+resid -> f32 ldc 512 (guarded)
template<int KTOT, int EPI>
__global__ void __launch_bounds__(256, 2)
gemm_v3(const __nv_bfloat16* __restrict__ A,
        const __nv_bfloat16* __restrict__ B,
        const float* __restrict__ bias,
        const float* __restrict__ resid,
        __nv_bfloat16* __restrict__ Cb,
        float* __restrict__ Cf)
{
    constexpr int NT = KTOT / V3KC;
    extern __shared__ __nv_bfloat16 gsm[];

    const int tid  = threadIdx.x;
    const int lane = tid & 31, wid = tid >> 5;
    const int wm   = wid & 1, wn = wid >> 1;
    const int m_blk = blockIdx.y * 128, n_blk = blockIdx.x * 128;
    const unsigned sbase = (unsigned)__cvta_generic_to_shared(gsm);

    float acc[4][4][4];
    #pragma unroll
    for (int a = 0; a < 4; a++)
        #pragma unroll
        for (int b = 0; b < 4; b++)
            #pragma unroll
            for (int c = 0; c < 4; c++) acc[a][b][c] = 0.f;

    auto load_tile = [&](int st, int k0) {
        const unsigned sa = sbase + st * V3STAGE_B;
        const unsigned sb = sa + V3TILE_B;
        #pragma unroll
        for (int i = tid; i < 1024; i += 256) {
            int r = i >> 3, c = i & 7;
            unsigned off = (unsigned)(r * V3SRG + c * 8) * 2;
            cp_async16(sa + off, A + (size_t)(m_blk + r) * KTOT + k0 + c * 8);
            cp_async16(sb + off, B + (size_t)(n_blk + r) * KTOT + k0 + c * 8);
        }
        cp_commit();
    };

    load_tile(0, 0);
    if (NT > 1) load_tile(1, V3KC);

    #pragma unroll 1
    for (int t = 0; t < NT; t++) {
        if (t + 1 < NT) cp_wait1(); else cp_wait0();
        __syncthreads();
        if (t + 2 < NT) load_tile((t + 2) % 3, (t + 2) * V3KC);

        const unsigned sa = sbase + (t % 3) * V3STAGE_B;
        const unsigned sb = sa + V3TILE_B;

        unsigned ra[2][4][4], rb[2][2][4];
        auto ldf = [&](int ks, int pb) {
            #pragma unroll
            for (int mt = 0; mt < 4; mt++)
                ldsm4(ra[pb][mt], sa + (unsigned)((wm * 64 + mt * 16 + (lane & 15)) * V3SRG +
                                                  ks + (lane >> 4) * 8) * 2);
            #pragma unroll
            for (int q = 0; q < 2; q++)
                ldsm4(rb[pb][q], sb + (unsigned)((wn * 32 + q * 16 + (lane & 15)) * V3SRG +
                                                 ks + (lane >> 4) * 8) * 2);
        };

        ldf(0, 0);
        #pragma unroll
        for (int ksi = 0; ksi < V3KC / 16; ksi++) {
            if (ksi + 1 < V3KC / 16) ldf((ksi + 1) * 16, (ksi + 1) & 1);
            const int pb = ksi & 1;
            #pragma unroll
            for (int mt = 0; mt < 4; mt++)
                #pragma unroll
                for (int nt = 0; nt < 4; nt++) {
                    unsigned bfrag[2] = { rb[pb][nt >> 1][nt & 1],
                                          rb[pb][nt >> 1][(nt & 1) + 2] };
                    mma16816(acc[mt][nt], ra[pb][mt], bfrag);
                }
        }
    }

    const int tr = lane >> 2, tc = (lane & 3) * 2;
    #pragma unroll
    for (int mt = 0; mt < 4; mt++) {
        #pragma unroll
        for (int nt = 0; nt < 4; nt++) {
            int col = n_blk + wn * 32 + nt * 8 + tc;
            float b0 = bias[col], b1 = bias[col + 1];
            #pragma unroll
            for (int h = 0; h < 2; h++) {
                int row = m_blk + wm * 64 + mt * 16 + tr + h * 8;
                float v0 = acc[mt][nt][h * 2 + 0] + b0;
                float v1 = acc[mt][nt][h * 2 + 1] + b1;
                if (EPI == 1) {
                    __nv_bfloat162 p = __floats2bfloat162_rn(gelu_exact(v0), gelu_exact(v1));
                    *reinterpret_cast<__nv_bfloat162*>(Cb + (size_t)row * 1024 + col) = p;
                } else {
                    if (row < MROWS) {
                        const float2 rx = *reinterpret_cast<const float2*>(resid + (size_t)row * 512 + col);
                        float2 o; o.x = v0 + rx.x; o.y = v1 + rx.y;
                        *reinterpret_cast<float2*>(Cf + (size_t)row * 512 + col) = o;
                    }
                }
            }
        }
    }
}

// ============================ v5 GEMM: 128 thr, 128x64 (small-K) ============================
#define V5KC 64
#define V5STAGE_B 24576u
#define V5SMEM (2 * 24576)

// EPI 4: +bias -> f32 ldc 512, row-guarded (pre-offset); EPI 5: +bias -> bf16 ldc 384
template<int KTOT, int EPI>
__global__ void __launch_bounds__(128, 4)
gemm_v5(const __nv_bfloat16* __restrict__ A,
        const __nv_bfloat16* __restrict__ B,
        const float* __restrict__ bias,
        __nv_bfloat16* __restrict__ Cb,
        float* __restrict__ Cf)
{
    constexpr int NT = KTOT / V5KC;
    extern __shared__ __nv_bfloat16 gsm[];

    const int tid  = threadIdx.x;
    const int lane = tid & 31, wid = tid >> 5;
    const int wm   = wid & 1, wn = wid >> 1;
    const int m_blk = blockIdx.y * 128, n_blk = blockIdx.x * 64;
    const unsigned sbase = (unsigned)__cvta_generic_to_shared(gsm);

    float acc[4][4][4];
    #pragma unroll
    for (int a = 0; a < 4; a++)
        #pragma unroll
        for (int b = 0; b < 4; b++)
            #pragma unroll
            for (int c = 0; c < 4; c++) acc[a][b][c] = 0.f;

    auto load_tile = [&](int st, int k0) {
        const unsigned sb = sbase + st * V5STAGE_B;
        #pragma unroll
        for (int j = 0; j < 12; j++) {
            int i = tid + j * 128;
            int r = i >> 3, c = i & 7;
            unsigned off = SWZ128((unsigned)(r * 128 + c * 16));
            const __nv_bfloat16* src = (r < 128)
                ? A + (size_t)(m_blk + r) * KTOT + k0 + c * 8
                : B + (size_t)(n_blk + (r - 128)) * KTOT + k0 + c * 8;
            cp_async16(sb + off, src);
        }
        cp_commit();
    };

    load_tile(0, 0);
    if (NT > 1) load_tile(1, V5KC);

    #pragma unroll 1
    for (int t = 0; t < NT; t++) {
        if (t + 1 < NT) cp_wait1(); else cp_wait0();
        __syncthreads();

        const unsigned sb = sbase + (t & 1) * V5STAGE_B;

        unsigned ra[2][4][4], rb[2][2][4];
        auto ldf = [&](int ks, int pb) {
            const unsigned kb = (unsigned)((ks + (lane >> 4) * 8) * 2);
            #pragma unroll
            for (int mt = 0; mt < 4; mt++) {
                unsigned off = (unsigned)((wm * 64 + mt * 16 + (lane & 15)) * 128) + kb;
                ldsm4(ra[pb][mt], sb + SWZ128(off));
            }
            #pragma unroll
            for (int q = 0; q < 2; q++) {
                unsigned off = (unsigned)((128 + wn * 32 + q * 16 + (lane & 15)) * 128) + kb;
                ldsm4(rb[pb][q], sb + SWZ128(off));
            }
        };

        ldf(0, 0);
        #pragma unroll
        for (int ksi = 0; ksi < V5KC / 16; ksi++) {
            if (ksi + 1 < V5KC / 16) ldf((ksi + 1) * 16, (ksi + 1) & 1);
            const int pb = ksi & 1;
            #pragma unroll
            for (int mt = 0; mt < 4; mt++)
                #pragma unroll
                for (int nt = 0; nt < 4; nt++) {
                    unsigned bfrag[2] = { rb[pb][nt >> 1][nt & 1],
                                          rb[pb][nt >> 1][(nt & 1) + 2] };
                    mma16816(acc[mt][nt], ra[pb][mt], bfrag);
                }
        }

        if (t + 2 < NT) {
            __syncthreads();
            load_tile(t & 1, (t + 2) * V5KC);
        }
    }

    const int tr = lane >> 2, tc = (lane & 3) * 2;
    #pragma unroll
    for (int mt = 0; mt < 4; mt++) {
        #pragma unroll
        for (int nt = 0; nt < 4; nt++) {
            int col = n_blk + wn * 32 + nt * 8 + tc;
            float b0 = bias[col], b1 = bias[col + 1];
            #pragma unroll
            for (int h = 0; h < 2; h++) {
                int row = m_blk + wm * 64 + mt * 16 + tr + h * 8;
                float v0 = acc[mt][nt][h * 2 + 0] + b0;
                float v1 = acc[mt][nt][h * 2 + 1] + b1;
                if (EPI == 4) {
                    if (row < MROWS) {
                        float2 o; o.x = v0; o.y = v1;
                        *reinterpret_cast<float2*>(Cf + (size_t)row * 512 + col) = o;
                    }
                } else {   // EPI 5
                    __nv_bfloat162 p = __floats2bfloat162_rn(v0, v1);
                    *reinterpret_cast<__nv_bfloat162*>(Cb + (size_t)row * 384 + col) = p;
                }
            }
        }
    }
}

// ============================ LAUNCH ============================
extern "C" void kernel_launch(void* const* d_in, const int* in_sizes, int n_in,
                              void* d_out, int out_size)
{
    const float* x     = (const float*)d_in[0];
    const float* tm_w1 = (const float*)d_in[1];
    const float* tm_b1 = (const float*)d_in[2];
    const float* tm_w2 = (const float*)d_in[3];
    const float* tm_b2 = (const float*)d_in[4];
    const float* na_w  = (const float*)d_in[5];
    const float* in_w  = (const float*)d_in[6];
    const float* in_b  = (const float*)d_in[7];
    const float* out_w = (const float*)d_in[8];
    const float* out_b = (const float*)d_in[9];
    const float* nf_w  = (const float*)d_in[10];
    const float* cm_w1 = (const float*)d_in[11];
    const float* cm_b1 = (const float*)d_in[12];
    const float* cm_w2 = (const float*)d_in[13];
    const float* cm_b2 = (const float*)d_in[14];
    float* out = (float*)d_out;

    static bool init_done = false;
    static cudaStream_t s2;
    static cudaEvent_t evFork, evConv, evJoin;
    if (!init_done) {
        cudaFuncSetAttribute(gemm_v3<512, 1>,
                             cudaFuncAttributeMaxDynamicSharedMemorySize, V3SMEM);
        cudaFuncSetAttribute(gemm_v3<1024, 2>,
                             cudaFuncAttributeMaxDynamicSharedMemorySize, V3SMEM);
        cudaFuncSetAttribute(gemm_v5<128, 4>,
                             cudaFuncAttributeMaxDynamicSharedMemorySize, V5SMEM);
        cudaFuncSetAttribute(gemm_v5<128, 5>,
                             cudaFuncAttributeMaxDynamicSharedMemorySize, V5SMEM);
        cudaStreamCreateWithFlags(&s2, cudaStreamNonBlocking);
        cudaEventCreateWithFlags(&evFork, cudaEventDisableTiming);
        cudaEventCreateWithFlags(&evConv, cudaEventDisableTiming);
        cudaEventCreateWithFlags(&evJoin, cudaEventDisableTiming);
        init_done = true;
    }

    __nv_bfloat16 *p_xn, *p_h, *p_xa, *p_o, *p_wqb, *p_wob, *p_w1, *p_w2, *p_qkv;
    float *p_xc;
    cudaGetSymbolAddress((void**)&p_xn,  g_xn);
    cudaGetSymbolAddress((void**)&p_h,   g_h);
    cudaGetSymbolAddress((void**)&p_w1,  g_w1);
    cudaGetSymbolAddress((void**)&p_w2,  g_w2);
    cudaGetSymbolAddress((void**)&p_xa,  g_xa);
    cudaGetSymbolAddress((void**)&p_o,   g_o);
    cudaGetSymbolAddress((void**)&p_wqb, g_wqb);
    cudaGetSymbolAddress((void**)&p_wob, g_wob);
    cudaGetSymbolAddress((void**)&p_qkv, g_qkv);
    cudaGetSymbolAddress((void**)&p_xc,  g_xc);

    // fork: s2 runs convert + token mixer; s0 starts attention immediately
    cudaEventRecord(evFork, 0);
    cudaStreamWaitEvent(s2, evFork, 0);
    convert_weights<<<2048, 256, 0, s2>>>(cm_w1, cm_w2, in_w, out_w);
    cudaEventRecord(evConv, s2);
    k1_mix<<<BT, 384, 0, s2>>>(x, tm_w1, tm_b1, tm_w2, tm_b2);
    cudaEventRecord(evJoin, s2);

    // main stream: attention chain (gq needs converted weights)
    k1_xa<<<BT, 128>>>(x, na_w);
    cudaStreamWaitEvent(0, evConv, 0);
    dim3 gq(6, MPADT);
    gemm_v5<128, 5><<<gq, 128, V5SMEM>>>(p_xa, p_wqb, in_b, p_qkv, nullptr);
    k_att2<<<BT, 128>>>();
    dim3 go(2, MPADT);
    gemm_v5<128, 4><<<go, 128, V5SMEM>>>(p_o, p_wob, out_b, nullptr, p_xc + DM);

    // join mixer; k_norm needs both g_xc halves
    cudaStreamWaitEvent(0, evJoin, 0);
    k_norm<<<MROWS / 8, 256>>>(nf_w);

    dim3 g1(8, MPADT), g2(4, MPADT);
    gemm_v3<512, 1><<<g1, 256, V3SMEM>>>(p_xn, p_w1, cm_b1, nullptr, p_h, nullptr);
    gemm_v3<1024, 2><<<g2, 256, V3SMEM>>>(p_h, p_w2, cm_b2, x, nullptr, out);
}

// round 16
// speedup vs baseline: 1.1327x; 1.1327x over previous
#include <cuda_runtime.h>
#include <cuda_bf16.h>
#include <cstdint>
#include <math.h>

#define NN 32
#define TT 243
#define VV 17
#define DD 512
#define DM 384
#define DA 128
#define NH 4
#define HD 32
#define BT (NN*TT)               // 7776 slices
#define ROW_ELEMS (VV*DD)
#define MROWS (BT*VV)            // 132192
#define MPADT 1033
#define MPAD  (MPADT*128)

typedef unsigned long long ull;

// ---- global scratch (static device arrays; zero-initialized) ----
__device__ __nv_bfloat16 g_xn [(size_t)MPAD * 512];
__device__ __nv_bfloat16 g_h  [(size_t)MPAD * 1024];
__device__ __nv_bfloat16 g_w1 [1024 * 512];
__device__ __nv_bfloat16 g_w2 [512 * 1024];
__device__ float         g_xc [(size_t)MROWS * 512];
__device__ __nv_bfloat16 g_xa [(size_t)MPAD * 128];
__device__ __nv_bfloat16 g_qkv[(size_t)MPAD * 384];
__device__ __nv_bfloat16 g_o  [(size_t)MPAD * 128];
__device__ __nv_bfloat16 g_wqb[384 * 128];
__device__ __nv_bfloat16 g_wob[128 * 128];

__device__ __forceinline__ ull pack2(float lo, float hi) {
    ull r; asm("mov.b64 %0, {%1, %2};" : "=l"(r) : "f"(lo), "f"(hi)); return r;
}
__device__ __forceinline__ float2 unpack2(ull v) {
    float2 r; asm("mov.b64 {%0, %1}, %2;" : "=f"(r.x), "=f"(r.y) : "l"(v)); return r;
}
__device__ __forceinline__ void ffma2(ull& acc, ull a, ull b) {
    asm("fma.rn.f32x2 %0, %1, %2, %0;" : "+l"(acc) : "l"(a), "l"(b));
}
__device__ __forceinline__ float gelu_exact(float v) {
    return 0.5f * v * (1.0f + erff(v * 0.7071067811865475f));
}
__device__ __forceinline__ void cp_commit() {
    asm volatile("cp.async.commit_group;" ::: "memory");
}
__device__ __forceinline__ void cp_wait0() { asm volatile("cp.async.wait_group 0;" ::: "memory"); }
__device__ __forceinline__ void cp_wait1() { asm volatile("cp.async.wait_group 1;" ::: "memory"); }
__device__ __forceinline__ void cp_async16(unsigned dst, const void* src) {
    asm volatile("cp.async.cg.shared.global [%0], [%1], 16;" :: "r"(dst), "l"(src));
}
#define SWZ128(off) ((off) ^ (((off) >> 3) & 0x70))

// ==================== weight convert ====================
extern "C" __global__ void convert_weights(const float* __restrict__ w1,
                                           const float* __restrict__ w2,
                                           const float* __restrict__ in_w,
                                           const float* __restrict__ out_w)
{
    int i = blockIdx.x * 256 + threadIdx.x;
    if (i < 1024 * 512) g_w1[i] = __float2bfloat16(w1[i]);
    if (i < 512 * 1024) g_w2[i] = __float2bfloat16(w2[i]);
    if (i < 384 * 128)  g_wqb[i] = __float2bfloat16(in_w[i]);
    if (i < 128 * 128)  g_wob[i] = __float2bfloat16(out_w[i]);
}

// ==================== K1a: token mixer (registers), 384 threads ====================
extern "C" __global__ void __launch_bounds__(384, 2)
k1_mix(const float* __restrict__ x,
       const float* __restrict__ tm_w1, const float* __restrict__ tm_b1,
       const float* __restrict__ tm_w2, const float* __restrict__ tm_b2)
{
    __shared__ float w1s[17 * 18], w2s[17 * 18], b1s[17], b2s[17];
    const int tid = threadIdx.x;
    const size_t base = (size_t)blockIdx.x * ROW_ELEMS;
    const float* xg = x + base;

    for (int i = tid; i < 289; i += 384) {
        int u = i / 17, v = i - u * 17;
        w1s[u * 18 + v] = tm_w1[i];
        w2s[u * 18 + v] = tm_w2[i];
    }
    if (tid < 17) { b1s[tid] = tm_b1[tid]; b2s[tid] = tm_b2[tid]; }
    __syncthreads();

    const int d = tid;
    float xr[17];
    #pragma unroll
    for (int v = 0; v < VV; v++) xr[v] = xg[v * DD + d];
    ull xp[8];
    #pragma unroll
    for (int p = 0; p < 8; p++) xp[p] = pack2(xr[2 * p], xr[2 * p + 1]);

    float h[17];
    #pragma unroll
    for (int u = 0; u < VV; u++) {
        ull a2 = 0ull;
        const float* wr = w1s + u * 18;
        #pragma unroll
        for (int p = 0; p < 8; p++) ffma2(a2, xp[p], *(const ull*)(wr + 2 * p));
        float2 s = unpack2(a2);
        h[u] = gelu_exact(s.x + s.y + xr[16] * wr[16] + b1s[u]);
    }
    ull hp[8];
    #pragma unroll
    for (int p = 0; p < 8; p++) hp[p] = pack2(h[2 * p], h[2 * p + 1]);

    float* oc = g_xc + (size_t)blockIdx.x * VV * DD + d;
    #pragma unroll
    for (int u = 0; u < VV; u++) {
        ull a2 = 0ull;
        const float* wr = w2s + u * 18;
        #pragma unroll
        for (int p = 0; p < 8; p++) ffma2(a2, hp[p], *(const ull*)(wr + 2 * p));
        float2 s = unpack2(a2);
        oc[(size_t)u * DD] = s.x + s.y + h[16] * wr[16] + b2s[u];
    }
}

// ==================== K1b: rmsnorm(xa) -> bf16, 128 threads ====================
extern "C" __global__ void __launch_bounds__(128, 8)
k1_xa(const float* __restrict__ x, const float* __restrict__ na_w)
{
    const int warp = threadIdx.x >> 5, lane = threadIdx.x & 31;
    const float* xg = x + (size_t)blockIdx.x * ROW_ELEMS + DM;
    for (int r = warp; r < VV; r += 4) {
        float vals[4]; float s = 0.f;
        #pragma unroll
        for (int q = 0; q < 4; q++) {
            float t = xg[r * DD + lane + 32 * q];
            vals[q] = t; s += t * t;
        }
        #pragma unroll
        for (int o = 16; o; o >>= 1) s += __shfl_xor_sync(0xffffffffu, s, o);
        float rms = rsqrtf(s * (1.0f / DA) + 1e-6f);
        __nv_bfloat16* oa = g_xa + ((size_t)blockIdx.x * VV + r) * DA;
        #pragma unroll
        for (int q = 0; q < 4; q++) {
            int c = lane + 32 * q;
            oa[c] = __float2bfloat16(vals[q] * rms * na_w[c]);
        }
    }
}

// ==================== K_att2: scores + softmax + o ====================
#define QLD 388
extern "C" __global__ void __launch_bounds__(128)
k_att2()
{
    __shared__ float qkv_s[VV * QLD];
    __shared__ float sc[NH * VV * VV];

    const int tid = threadIdx.x;
    const size_t bid = blockIdx.x;

    // load qkv rows (17 x 384 bf16) -> fp32 smem
    {
        const __nv_bfloat16* src = g_qkv + bid * (VV * 384);
        #pragma unroll 4
        for (int i = tid; i < VV * 48; i += 128) {
            int v = i / 48, c = i - v * 48;
            uint4 raw = *(const uint4*)(src + v * 384 + c * 8);
            const __nv_bfloat162* b2 = (const __nv_bfloat162*)&raw;
            float* dst = qkv_s + v * QLD + c * 8;
            #pragma unroll
            for (int q = 0; q < 4; q++) {
                float2 f = __bfloat1622float2(b2[q]);
                dst[2 * q] = f.x; dst[2 * q + 1] = f.y;
            }
        }
    }
    __syncthreads();

    for (int k = tid; k < NH * VV * VV; k += 128) {
        int h = k / (VV * VV), r = k - h * VV * VV, qv = r / VV, kv = r - qv * VV;
        const float4* qp = (const float4*)(qkv_s + qv * QLD + h * HD);
        const float4* kp = (const float4*)(qkv_s + kv * QLD + DA + h * HD);
        float s = 0.f;
        #pragma unroll
        for (int d = 0; d < 8; d++) {
            float4 a = qp[d], b = kp[d];
            s += a.x * b.x + a.y * b.y + a.z * b.z + a.w * b.w;
        }
        sc[k] = s * 0.17677669529663687f;
    }
    __syncthreads();

    for (int r = tid; r < NH * VV; r += 128) {
        float* row = sc + r * VV;
        float m = row[0];
        #pragma unroll
        for (int i = 1; i < VV; i++) m = fmaxf(m, row[i]);
        float s = 0.f;
        #pragma unroll
        for (int i = 0; i < VV; i++) { float e = __expf(row[i] - m); row[i] = e; s += e; }
        float inv = 1.f / s;
        #pragma unroll
        for (int i = 0; i < VV; i++) row[i] *= inv;
    }
    __syncthreads();

    // o = attn @ v, kv-outer loop: 306 LDS/thread instead of 578
    {
        const int dd = tid, h = dd >> 5;
        float acc[VV];
        #pragma unroll
        for (int vq = 0; vq < VV; vq++) acc[vq] = 0.f;
        #pragma unroll 1
        for (int kv = 0; kv < VV; kv++) {
            float v = qkv_s[kv * QLD + 2 * DA + dd];
            const float* sch = sc + h * VV * VV + kv;
            #pragma unroll
            for (int vq = 0; vq < VV; vq++)
                acc[vq] += sch[vq * VV] * v;   // warp-broadcast
        }
        __nv_bfloat16* og = g_o + bid * (VV * DA) + dd;
        #pragma unroll
        for (int vq = 0; vq < VV; vq++)
            og[(size_t)vq * DA] = __float2bfloat16(acc[vq]);
    }
}

// ==================== K_norm ====================
extern "C" __global__ void __launch_bounds__(256)
k_norm(const float* __restrict__ nf_w)
{
    const int warp = threadIdx.x >> 5, lane = threadIdx.x & 31;
    const size_t row = (size_t)blockIdx.x * 8 + warp;
    const float* src = g_xc + row * DD;
    float4 v[4]; float s = 0.f;
    #pragma unroll
    for (int q = 0; q < 4; q++) {
        v[q] = *(const float4*)(src + (lane + 32 * q) * 4);
        s += v[q].x * v[q].x + v[q].y * v[q].y + v[q].z * v[q].z + v[q].w * v[q].w;
    }
    #pragma unroll
    for (int o = 16; o; o >>= 1) s += __shfl_xor_sync(0xffffffffu, s, o);
    float r = rsqrtf(s * (1.0f / DD) + 1e-6f);
    __nv_bfloat16* dst = g_xn + row * DD;
    #pragma unroll
    for (int q = 0; q < 4; q++) {
        int c = (lane + 32 * q) * 4;
        const float4 wv = *(const float4*)(nf_w + c);
        __nv_bfloat162 p0 = __floats2bfloat162_rn(v[q].x * r * wv.x, v[q].y * r * wv.y);
        __nv_bfloat162 p1 = __floats2bfloat162_rn(v[q].z * r * wv.z, v[q].w * r * wv.w);
        *reinterpret_cast<__nv_bfloat162*>(dst + c)     = p0;
        *reinterpret_cast<__nv_bfloat162*>(dst + c + 2) = p1;
    }
}

// ============================ BF16 GEMM v5 ============================
// CTA tile 128(M)x64(N), 128 threads (4 warps, warp tile 64x32),
// KC=64, SW128 stages (24.6KB), 2 stages -> 4 CTAs/SM (16 warps/SM).
__device__ __forceinline__ void ldsm4(unsigned* r, unsigned addr) {
    asm volatile("ldmatrix.sync.aligned.m8n8.x4.shared.b16 {%0,%1,%2,%3}, [%4];"
        : "=r"(r[0]), "=r"(r[1]), "=r"(r[2]), "=r"(r[3]) : "r"(addr));
}
__device__ __forceinline__ void mma16816(float* c, const unsigned* a, const unsigned* b) {
    asm volatile("mma.sync.aligned.m16n8k16.row.col.f32.bf16.bf16.f32 "
        "{%0,%1,%2,%3}, {%4,%5,%6,%7}, {%8,%9}, {%0,%1,%2,%3};"
        : "+f"(c[0]), "+f"(c[1]), "+f"(c[2]), "+f"(c[3])
        : "r"(a[0]), "r"(a[1]), "r"(a[2]), "r"(a[3]), "r"(b[0]), "r"(b[1]));
}

#define KC 64
#define STAGE_BYTES 24576u            // (128 A-rows + 64 B-rows) * 128B, SW128
#define GSMEM_BYTES (2 * 24576)       // 49152 -> 4 CTAs/SM

// EPI: 1 = gelu(+bias) -> bf16 ldc 1024
//      2 = +bias+resid -> f32 ldc 512, row-guarded
//      4 = +bias -> f32 ldc 512, row-guarded (C pre-offset to col 384)
//      5 = +bias -> bf16 ldc 384
template<int KTOT, int EPI>
__global__ void __launch_bounds__(128, 4)
gemm_v5(const __nv_bfloat16* __restrict__ A,
        const __nv_bfloat16* __restrict__ B,
        const float* __restrict__ bias,
        const float* __restrict__ resid,
        __nv_bfloat16* __restrict__ Cb,
        float* __restrict__ Cf)
{
    constexpr int NT = KTOT / KC;
    extern __shared__ __nv_bfloat16 gsm[];

    const int tid  = threadIdx.x;
    const int lane = tid & 31, wid = tid >> 5;
    const int wm   = wid & 1, wn = wid >> 1;          // 2 x 2 warp grid
    const int m_blk = blockIdx.y * 128, n_blk = blockIdx.x * 64;
    const unsigned sbase = (unsigned)__cvta_generic_to_shared(gsm);

    float acc[4][4][4];
    #pragma unroll
    for (int a = 0; a < 4; a++)
        #pragma unroll
        for (int b = 0; b < 4; b++)
            #pragma unroll
            for (int c = 0; c < 4; c++) acc[a][b][c] = 0.f;

    // stage: rows 0..127 = A tile, rows 128..191 = B tile; 128B rows, SW128.
    auto load_tile = [&](int st, int k0) {
        const unsigned sb = sbase + st * STAGE_BYTES;
        #pragma unroll
        for (int j = 0; j < 12; j++) {
            int i = tid + j * 128;
            int r = i >> 3, c = i & 7;
            unsigned off = SWZ128((unsigned)(r * 128 + c * 16));
            const __nv_bfloat16* src = (r < 128)
                ? A + (size_t)(m_blk + r) * KTOT + k0 + c * 8
                : B + (size_t)(n_blk + (r - 128)) * KTOT + k0 + c * 8;
            cp_async16(sb + off, src);
        }
        cp_commit();
    };

    load_tile(0, 0);
    if (NT > 1) load_tile(1, KC);

    #pragma unroll 1
    for (int t = 0; t < NT; t++) {
        if (t + 1 < NT) cp_wait1(); else cp_wait0();
        __syncthreads();

        const unsigned sb = sbase + (t & 1) * STAGE_BYTES;

        unsigned ra[2][4][4], rb[2][2][4];
        auto ldf = [&](int ks, int pb) {
            const unsigned kb = (unsigned)((ks + (lane >> 4) * 8) * 2);
            #pragma unroll
            for (int mt = 0; mt < 4; mt++) {
                unsigned off = (unsigned)((wm * 64 + mt * 16 + (lane & 15)) * 128) + kb;
                ldsm4(ra[pb][mt], sb + SWZ128(off));
            }
            #pragma unroll
            for (int q = 0; q < 2; q++) {
                unsigned off = (unsigned)((128 + wn * 32 + q * 16 + (lane & 15)) * 128) + kb;
                ldsm4(rb[pb][q], sb + SWZ128(off));
            }
        };

        ldf(0, 0);
        #pragma unroll
        for (int ksi = 0; ksi < KC / 16; ksi++) {
            if (ksi + 1 < KC / 16) ldf((ksi + 1) * 16, (ksi + 1) & 1);
            const int pb = ksi & 1;
            #pragma unroll
            for (int mt = 0; mt < 4; mt++)
                #pragma unroll
                for (int nt = 0; nt < 4; nt++) {
                    unsigned bfrag[2] = { rb[pb][nt >> 1][nt & 1],
                                          rb[pb][nt >> 1][(nt & 1) + 2] };
                    mma16816(acc[mt][nt], ra[pb][mt], bfrag);
                }
        }

        // overwrite this buffer with tile t+2 only after everyone finished it
        if (t + 2 < NT) {
            __syncthreads();
            load_tile(t & 1, (t + 2) * KC);
        }
    }

    const int tr = lane >> 2, tc = (lane & 3) * 2;
    #pragma unroll
    for (int mt = 0; mt < 4; mt++) {
        #pragma unroll
        for (int nt = 0; nt < 4; nt++) {
            int col = n_blk + wn * 32 + nt * 8 + tc;
            float b0 = bias[col], b1 = bias[col + 1];
            #pragma unroll
            for (int h = 0; h < 2; h++) {
                int row = m_blk + wm * 64 + mt * 16 + tr + h * 8;
                float v0 = acc[mt][nt][h * 2 + 0] + b0;
                float v1 = acc[mt][nt][h * 2 + 1] + b1;
                if (EPI == 1) {
                    __nv_bfloat162 p = __floats2bfloat162_rn(gelu_exact(v0), gelu_exact(v1));
                    *reinterpret_cast<__nv_bfloat162*>(Cb + (size_t)row * 1024 + col) = p;
                } else if (EPI == 2) {
                    if (row < MROWS) {
                        const float2 rx = *reinterpret_cast<const float2*>(resid + (size_t)row * 512 + col);
                        float2 o; o.x = v0 + rx.x; o.y = v1 + rx.y;
                        *reinterpret_cast<float2*>(Cf + (size_t)row * 512 + col) = o;
                    }
                } else if (EPI == 4) {
                    if (row < MROWS) {
                        float2 o; o.x = v0; o.y = v1;
                        *reinterpret_cast<float2*>(Cf + (size_t)row * 512 + col) = o;
                    }
                } else {   // EPI 5: bf16, ldc 384
                    __nv_bfloat162 p = __floats2bfloat162_rn(v0, v1);
                    *reinterpret_cast<__nv_bfloat162*>(Cb + (size_t)row * 384 + col) = p;
                }
            }
        }
    }
}

// ============================ LAUNCH ============================
extern "C" void kernel_launch(void* const* d_in, const int* in_sizes, int n_in,
                              void* d_out, int out_size)
{
    const float* x     = (const float*)d_in[0];
    const float* tm_w1 = (const float*)d_in[1];
    const float* tm_b1 = (const float*)d_in[2];
    const float* tm_w2 = (const float*)d_in[3];
    const float* tm_b2 = (const float*)d_in[4];
    const float* na_w  = (const float*)d_in[5];
    const float* in_w  = (const float*)d_in[6];
    const float* in_b  = (const float*)d_in[7];
    const float* out_w = (const float*)d_in[8];
    const float* out_b = (const float*)d_in[9];
    const float* nf_w  = (const float*)d_in[10];
    const float* cm_w1 = (const float*)d_in[11];
    const float* cm_b1 = (const float*)d_in[12];
    const float* cm_w2 = (const float*)d_in[13];
    const float* cm_b2 = (const float*)d_in[14];
    float* out = (float*)d_out;

    static bool init_done = false;
    static cudaStream_t s2;
    static cudaEvent_t evFork, evConv, evJoin;
    if (!init_done) {
        cudaFuncSetAttribute(gemm_v5<512, 1>,
                             cudaFuncAttributeMaxDynamicSharedMemorySize, GSMEM_BYTES);
        cudaFuncSetAttribute(gemm_v5<1024, 2>,
                             cudaFuncAttributeMaxDynamicSharedMemorySize, GSMEM_BYTES);
        cudaFuncSetAttribute(gemm_v5<128, 4>,
                             cudaFuncAttributeMaxDynamicSharedMemorySize, GSMEM_BYTES);
        cudaFuncSetAttribute(gemm_v5<128, 5>,
                             cudaFuncAttributeMaxDynamicSharedMemorySize, GSMEM_BYTES);
        cudaStreamCreateWithFlags(&s2, cudaStreamNonBlocking);
        cudaEventCreateWithFlags(&evFork, cudaEventDisableTiming);
        cudaEventCreateWithFlags(&evConv, cudaEventDisableTiming);
        cudaEventCreateWithFlags(&evJoin, cudaEventDisableTiming);
        init_done = true;
    }

    __nv_bfloat16 *p_xn, *p_h, *p_xa, *p_o, *p_wqb, *p_wob, *p_w1, *p_w2, *p_qkv;
    float *p_xc;
    cudaGetSymbolAddress((void**)&p_xn,  g_xn);
    cudaGetSymbolAddress((void**)&p_h,   g_h);
    cudaGetSymbolAddress((void**)&p_w1,  g_w1);
    cudaGetSymbolAddress((void**)&p_w2,  g_w2);
    cudaGetSymbolAddress((void**)&p_xa,  g_xa);
    cudaGetSymbolAddress((void**)&p_o,   g_o);
    cudaGetSymbolAddress((void**)&p_wqb, g_wqb);
    cudaGetSymbolAddress((void**)&p_wob, g_wob);
    cudaGetSymbolAddress((void**)&p_qkv, g_qkv);
    cudaGetSymbolAddress((void**)&p_xc,  g_xc);

    // fork: s2 runs convert + token mixer; s0 starts attention immediately
    cudaEventRecord(evFork, 0);
    cudaStreamWaitEvent(s2, evFork, 0);
    convert_weights<<<2048, 256, 0, s2>>>(cm_w1, cm_w2, in_w, out_w);
    cudaEventRecord(evConv, s2);
    k1_mix<<<BT, 384, 0, s2>>>(x, tm_w1, tm_b1, tm_w2, tm_b2);
    cudaEventRecord(evJoin, s2);

    // main stream: attention chain (gq needs converted weights)
    k1_xa<<<BT, 128>>>(x, na_w);
    cudaStreamWaitEvent(0, evConv, 0);
    dim3 gq(6, MPADT);
    gemm_v5<128, 5><<<gq, 128, GSMEM_BYTES>>>(p_xa, p_wqb, in_b, nullptr, p_qkv, nullptr);
    k_att2<<<BT, 128>>>();
    dim3 go(2, MPADT);
    gemm_v5<128, 4><<<go, 128, GSMEM_BYTES>>>(p_o, p_wob, out_b, nullptr, nullptr, p_xc + DM);

    // join mixer; k_norm needs both g_xc halves
    cudaStreamWaitEvent(0, evJoin, 0);
    k_norm<<<MROWS / 8, 256>>>(nf_w);

    dim3 g1(16, MPADT), g2(8, MPADT);
    gemm_v5<512, 1><<<g1, 128, GSMEM_BYTES>>>(p_xn, p_w1, cm_b1, nullptr, p_h, nullptr);
    gemm_v5<1024, 2><<<g2, 128, GSMEM_BYTES>>>(p_h, p_w2, cm_b2, x, nullptr, out);
}